// round 2
// baseline (speedup 1.0000x reference)
#include <cuda_runtime.h>
#include <cuda_bf16.h>
#include <math.h>

// Problem constants (fixed by the reference)
#define NE 16          // experts
#define NW 3           // local window
#define NB 64          // batch
#define NP 4096        // patches per expert
#define BP (NB * NP)   // 262144 elements per (expert, projection) plane
#define QP4 (BP / 4)   // plane size in float4 units = 65536
#define P4  (NP / 4)   // 1024

// out[b, e*P + p] = softmax_w( Qm[e]*Km[route[e][w]] / (sqrt(128)*|T|) * gate[e][w] ) . Vm[route[e][w]]
// Qm/Km/Vm = mean over the 2 projections.

__global__ void __launch_bounds__(256)
cantor_attn_kernel(const float4* __restrict__ Qp,
                   const float4* __restrict__ Kp,
                   const float4* __restrict__ Vp,
                   const float*  __restrict__ betas,
                   const float*  __restrict__ temperature,
                   const int*    __restrict__ routes,
                   float4*       __restrict__ out)
{
    __shared__ int   s_route[NW];
    __shared__ float s_gate[NW];
    __shared__ float s_inv;

    const int e = blockIdx.x >> 8;              // 256 blocks per expert
    const int t = threadIdx.x;

    if (t < NW) {
        const int r = routes[e * NW + t];
        s_route[t] = r;
        s_gate[t]  = (r != e) ? (1.0f / (1.0f + __expf(-betas[e * NW + t]))) : 1.0f;
    }
    if (t == NW) {
        s_inv = 1.0f / (sqrtf(128.0f) * fabsf(temperature[0]));
    }
    __syncthreads();

    const int idx4 = ((blockIdx.x & 255) << 8) + t;   // in [0, QP4)
    const int b    = idx4 >> 10;                       // / P4
    const int p4   = idx4 & (P4 - 1);

    const int   r0 = s_route[0], r1 = s_route[1], r2 = s_route[2];
    const float g0 = s_gate[0],  g1 = s_gate[1],  g2 = s_gate[2];
    const float inv = s_inv;

    // Q mean over the 2 projections
    const float4 qa = Qp[(long)(e * 2)     * QP4 + idx4];
    const float4 qb = Qp[(long)(e * 2 + 1) * QP4 + idx4];

    // neighbor K projections
    const float4 k0a = Kp[(long)(r0 * 2)     * QP4 + idx4];
    const float4 k0b = Kp[(long)(r0 * 2 + 1) * QP4 + idx4];
    const float4 k1a = Kp[(long)(r1 * 2)     * QP4 + idx4];
    const float4 k1b = Kp[(long)(r1 * 2 + 1) * QP4 + idx4];
    const float4 k2a = Kp[(long)(r2 * 2)     * QP4 + idx4];
    const float4 k2b = Kp[(long)(r2 * 2 + 1) * QP4 + idx4];

    // neighbor V projections
    const float4 v0a = Vp[(long)(r0 * 2)     * QP4 + idx4];
    const float4 v0b = Vp[(long)(r0 * 2 + 1) * QP4 + idx4];
    const float4 v1a = Vp[(long)(r1 * 2)     * QP4 + idx4];
    const float4 v1b = Vp[(long)(r1 * 2 + 1) * QP4 + idx4];
    const float4 v2a = Vp[(long)(r2 * 2)     * QP4 + idx4];
    const float4 v2b = Vp[(long)(r2 * 2 + 1) * QP4 + idx4];

    float4 res;

#define DO_LANE(c)                                                         \
    {                                                                      \
        const float q  = 0.5f * (qa.c + qb.c);                             \
        const float k0 = 0.5f * (k0a.c + k0b.c);                           \
        const float k1 = 0.5f * (k1a.c + k1b.c);                           \
        const float k2 = 0.5f * (k2a.c + k2b.c);                           \
        const float v0 = 0.5f * (v0a.c + v0b.c);                           \
        const float v1 = 0.5f * (v1a.c + v1b.c);                           \
        const float v2 = 0.5f * (v2a.c + v2b.c);                           \
        const float qi = q * inv;                                          \
        const float s0 = qi * k0 * g0;                                     \
        const float s1 = qi * k1 * g1;                                     \
        const float s2 = qi * k2 * g2;                                     \
        const float m  = fmaxf(fmaxf(s0, s1), s2);                         \
        const float x0 = __expf(s0 - m);                                   \
        const float x1 = __expf(s1 - m);                                   \
        const float x2 = __expf(s2 - m);                                   \
        const float rs = 1.0f / (x0 + x1 + x2);                            \
        res.c = (x0 * v0 + x1 * v1 + x2 * v2) * rs;                        \
    }

    DO_LANE(x)
    DO_LANE(y)
    DO_LANE(z)
    DO_LANE(w)
#undef DO_LANE

    // out[b, e*NP + p] as float4
    out[(long)b * (NE * P4) + (long)e * P4 + p4] = res;
}

extern "C" void kernel_launch(void* const* d_in, const int* in_sizes, int n_in,
                              void* d_out, int out_size)
{
    // metadata order: Q_proj, K_proj, V_proj, betas, temperature, routes, num_patches
    const float4* Qp    = (const float4*)d_in[0];
    const float4* Kp    = (const float4*)d_in[1];
    const float4* Vp    = (const float4*)d_in[2];
    const float*  betas = (const float*)d_in[3];
    const float*  temp  = (const float*)d_in[4];
    const int*    routes= (const int*)d_in[5];
    float4*       out   = (float4*)d_out;

    (void)in_sizes; (void)n_in; (void)out_size;

    const int threads = 256;
    const int blocks  = NE * (QP4 / threads);   // 16 * 256 = 4096
    cantor_attn_kernel<<<blocks, threads>>>(Qp, Kp, Vp, betas, temp, routes, out);
}

// round 3
// speedup vs baseline: 1.0616x; 1.0616x over previous
#include <cuda_runtime.h>
#include <cuda_bf16.h>
#include <math.h>

// Problem constants (fixed by the reference)
#define NE 16          // experts
#define NW 3           // local window
#define NB 64          // batch
#define NP 4096        // patches per expert
#define BP (NB * NP)   // 262144 elements per (expert, projection) plane
#define HBP (BP / 2)   // plane size in float2 units = 131072
#define HP (NP / 2)    // 2048

// out[b, e*NP + p] = softmax_w( Qm[e]*Km[route[e][w]] / (sqrt(128)*|T|) * gate[e][w] ) . Vm[route[e][w]]
// Qm/Km/Vm = mean over the 2 projections.

__global__ void __launch_bounds__(256)
cantor_attn_kernel(const float2* __restrict__ Qp,
                   const float2* __restrict__ Kp,
                   const float2* __restrict__ Vp,
                   const float*  __restrict__ betas,
                   const float*  __restrict__ temperature,
                   const int*    __restrict__ routes,
                   float2*       __restrict__ out)
{
    // 512 blocks per expert (512 * 256 = 131072 = HBP)
    const int e    = blockIdx.x >> 9;
    const int idx2 = ((blockIdx.x & 511) << 8) + threadIdx.x;   // in [0, HBP)

    // Uniform (warp-broadcast) scalar setup — no shared memory, no barrier.
    const int r0 = routes[e * NW + 0];
    const int r1 = routes[e * NW + 1];
    const int r2 = routes[e * NW + 2];
    const float g0 = (r0 != e) ? (1.0f / (1.0f + __expf(-betas[e * NW + 0]))) : 1.0f;
    const float g1 = (r1 != e) ? (1.0f / (1.0f + __expf(-betas[e * NW + 1]))) : 1.0f;
    const float g2 = (r2 != e) ? (1.0f / (1.0f + __expf(-betas[e * NW + 2]))) : 1.0f;
    const float inv = 1.0f / (sqrtf(128.0f) * fabsf(temperature[0]));

    // Q mean over the 2 projections
    const float2 qa = Qp[(long)(e * 2)     * HBP + idx2];
    const float2 qb = Qp[(long)(e * 2 + 1) * HBP + idx2];

    // neighbor K projections
    const float2 k0a = Kp[(long)(r0 * 2)     * HBP + idx2];
    const float2 k0b = Kp[(long)(r0 * 2 + 1) * HBP + idx2];
    const float2 k1a = Kp[(long)(r1 * 2)     * HBP + idx2];
    const float2 k1b = Kp[(long)(r1 * 2 + 1) * HBP + idx2];
    const float2 k2a = Kp[(long)(r2 * 2)     * HBP + idx2];
    const float2 k2b = Kp[(long)(r2 * 2 + 1) * HBP + idx2];

    // neighbor V projections
    const float2 v0a = Vp[(long)(r0 * 2)     * HBP + idx2];
    const float2 v0b = Vp[(long)(r0 * 2 + 1) * HBP + idx2];
    const float2 v1a = Vp[(long)(r1 * 2)     * HBP + idx2];
    const float2 v1b = Vp[(long)(r1 * 2 + 1) * HBP + idx2];
    const float2 v2a = Vp[(long)(r2 * 2)     * HBP + idx2];
    const float2 v2b = Vp[(long)(r2 * 2 + 1) * HBP + idx2];

    float2 res;

#define DO_LANE(c)                                                         \
    {                                                                      \
        const float q  = 0.5f * (qa.c + qb.c);                             \
        const float k0 = 0.5f * (k0a.c + k0b.c);                           \
        const float k1 = 0.5f * (k1a.c + k1b.c);                           \
        const float k2 = 0.5f * (k2a.c + k2b.c);                           \
        const float v0 = 0.5f * (v0a.c + v0b.c);                           \
        const float v1 = 0.5f * (v1a.c + v1b.c);                           \
        const float v2 = 0.5f * (v2a.c + v2b.c);                           \
        const float qi = q * inv;                                          \
        const float s0 = qi * k0 * g0;                                     \
        const float s1 = qi * k1 * g1;                                     \
        const float s2 = qi * k2 * g2;                                     \
        const float m  = fmaxf(fmaxf(s0, s1), s2);                         \
        const float x0 = __expf(s0 - m);                                   \
        const float x1 = __expf(s1 - m);                                   \
        const float x2 = __expf(s2 - m);                                   \
        const float rs = 1.0f / (x0 + x1 + x2);                            \
        res.c = (x0 * v0 + x1 * v1 + x2 * v2) * rs;                        \
    }

    DO_LANE(x)
    DO_LANE(y)
#undef DO_LANE

    // out[b, e*NP + p] as float2: b = idx2 / HP, p2 = idx2 % HP
    const int b  = idx2 >> 11;          // / HP (2048)
    const int p2 = idx2 & (HP - 1);
    out[(long)b * (NE * HP) + (long)e * HP + p2] = res;
}

extern "C" void kernel_launch(void* const* d_in, const int* in_sizes, int n_in,
                              void* d_out, int out_size)
{
    // metadata order: Q_proj, K_proj, V_proj, betas, temperature, routes, num_patches
    const float2* Qp    = (const float2*)d_in[0];
    const float2* Kp    = (const float2*)d_in[1];
    const float2* Vp    = (const float2*)d_in[2];
    const float*  betas = (const float*)d_in[3];
    const float*  temp  = (const float*)d_in[4];
    const int*    routes= (const int*)d_in[5];
    float2*       out   = (float2*)d_out;

    (void)in_sizes; (void)n_in; (void)out_size;

    const int threads = 256;
    const int blocks  = NE * (HBP / threads);   // 16 * 512 = 8192
    cantor_attn_kernel<<<blocks, threads>>>(Qp, Kp, Vp, betas, temp, routes, out);
}

// round 4
// speedup vs baseline: 1.1325x; 1.0668x over previous
#include <cuda_runtime.h>
#include <cuda_bf16.h>
#include <math.h>

// Problem constants (fixed by the reference)
#define NE 16          // experts
#define NW 3           // local window
#define NB 64          // batch
#define NP 4096        // patches per expert
#define BP (NB * NP)   // 262144 elements per (expert, projection) plane
#define HBP (BP / 2)   // plane size in float2 units = 131072
#define HP (NP / 2)    // 2048
#define EG 4           // experts handled per thread

__global__ void __launch_bounds__(256)
cantor_attn_kernel(const float2* __restrict__ Qp,
                   const float2* __restrict__ Kp,
                   const float2* __restrict__ Vp,
                   const float*  __restrict__ betas,
                   const float*  __restrict__ temperature,
                   const int*    __restrict__ routes,
                   float2*       __restrict__ out)
{
    // 512 plane-blocks per expert-group; NE/EG = 4 groups -> 2048 blocks
    const int g    = blockIdx.x >> 9;                         // expert group
    const int idx2 = ((blockIdx.x & 511) << 8) + threadIdx.x; // in [0, HBP)

    const float inv = 1.0f / (sqrtf(128.0f) * fabsf(temperature[0]));

    const int b  = idx2 >> 11;          // / HP
    const int p2 = idx2 & (HP - 1);
    const long obase = (long)b * (NE * HP) + p2;

    #pragma unroll
    for (int e = g * EG; e < g * EG + EG; e++) {
        const int r0 = routes[e * NW + 0];
        const int r1 = routes[e * NW + 1];
        const int r2 = routes[e * NW + 2];
        const float g0 = (r0 != e) ? __fdividef(1.0f, 1.0f + __expf(-betas[e * NW + 0])) : 1.0f;
        const float g1 = (r1 != e) ? __fdividef(1.0f, 1.0f + __expf(-betas[e * NW + 1])) : 1.0f;
        const float g2 = (r2 != e) ? __fdividef(1.0f, 1.0f + __expf(-betas[e * NW + 2])) : 1.0f;

        // Q mean over the 2 projections
        const float2 qa = Qp[(long)(e * 2)     * HBP + idx2];
        const float2 qb = Qp[(long)(e * 2 + 1) * HBP + idx2];

        // neighbor K projections (L1 hits when neighbors repeat across the group)
        const float2 k0a = Kp[(long)(r0 * 2)     * HBP + idx2];
        const float2 k0b = Kp[(long)(r0 * 2 + 1) * HBP + idx2];
        const float2 k1a = Kp[(long)(r1 * 2)     * HBP + idx2];
        const float2 k1b = Kp[(long)(r1 * 2 + 1) * HBP + idx2];
        const float2 k2a = Kp[(long)(r2 * 2)     * HBP + idx2];
        const float2 k2b = Kp[(long)(r2 * 2 + 1) * HBP + idx2];

        // neighbor V projections
        const float2 v0a = Vp[(long)(r0 * 2)     * HBP + idx2];
        const float2 v0b = Vp[(long)(r0 * 2 + 1) * HBP + idx2];
        const float2 v1a = Vp[(long)(r1 * 2)     * HBP + idx2];
        const float2 v1b = Vp[(long)(r1 * 2 + 1) * HBP + idx2];
        const float2 v2a = Vp[(long)(r2 * 2)     * HBP + idx2];
        const float2 v2b = Vp[(long)(r2 * 2 + 1) * HBP + idx2];

        float2 res;

#define DO_LANE(c)                                                         \
        {                                                                  \
            const float q  = 0.5f * (qa.c + qb.c);                         \
            const float k0 = 0.5f * (k0a.c + k0b.c);                       \
            const float k1 = 0.5f * (k1a.c + k1b.c);                       \
            const float k2 = 0.5f * (k2a.c + k2b.c);                       \
            const float v0 = 0.5f * (v0a.c + v0b.c);                       \
            const float v1 = 0.5f * (v1a.c + v1b.c);                       \
            const float v2 = 0.5f * (v2a.c + v2b.c);                       \
            const float qi = q * inv;                                      \
            const float s0 = qi * k0 * g0;                                 \
            const float s1 = qi * k1 * g1;                                 \
            const float s2 = qi * k2 * g2;                                 \
            const float m  = fmaxf(fmaxf(s0, s1), s2);                     \
            const float x0 = __expf(s0 - m);                               \
            const float x1 = __expf(s1 - m);                               \
            const float x2 = __expf(s2 - m);                               \
            const float rs = __fdividef(1.0f, x0 + x1 + x2);               \
            res.c = (x0 * v0 + x1 * v1 + x2 * v2) * rs;                    \
        }

        DO_LANE(x)
        DO_LANE(y)
#undef DO_LANE

        out[obase + (long)e * HP] = res;
    }
}

extern "C" void kernel_launch(void* const* d_in, const int* in_sizes, int n_in,
                              void* d_out, int out_size)
{
    // metadata order: Q_proj, K_proj, V_proj, betas, temperature, routes, num_patches
    const float2* Qp    = (const float2*)d_in[0];
    const float2* Kp    = (const float2*)d_in[1];
    const float2* Vp    = (const float2*)d_in[2];
    const float*  betas = (const float*)d_in[3];
    const float*  temp  = (const float*)d_in[4];
    const int*    routes= (const int*)d_in[5];
    float2*       out   = (float2*)d_out;

    (void)in_sizes; (void)n_in; (void)out_size;

    const int threads = 256;
    const int blocks  = (NE / EG) * (HBP / threads);   // 4 * 512 = 2048
    cantor_attn_kernel<<<blocks, threads>>>(Qp, Kp, Vp, betas, temp, routes, out);
}